// round 14
// baseline (speedup 1.0000x reference)
#include <cuda_runtime.h>

// Gaussian_Forward_Model: 3x3 conv, padding=1 (zeros), kernel built from
// weight (clamped) * weight_factor (clamped), rounded (RNE), min-clamped.
// input: [B=64, C=1, H=512, W=512] fp32
// output: [N_MULT, B, 1, H, W] fp32
//
// R9: R8's structure (ROWS=8, plain stores, interior specialization) with
// the scalar-halo loads replaced by warp shuffles. Ledger: R4 (shuffle+stcs)
// beat R7 (scalar+stcs) by 3.2us; stcs costs ~6us (R7 vs R8). This is the
// untested shuffle+plain-store cell. Scalar halo loads cost ~8 L1tex
// wavefronts per warp-row; SHFL moves that off the L1tex queue.

#define B 64
#define H 512
#define W 512
#define ROWS 8              // output rows per thread
#define TPB 128             // 128 threads * 4 floats = 512 = W

__device__ __forceinline__ float clampf(float v, float lo, float hi) {
    return fminf(fmaxf(v, lo), hi);
}

struct Row {
    float l;    // x-1
    float4 c;   // x..x+3
    float r;    // x+4
};

// Load one row: central float4 per lane; +/-1 halo via warp shuffle.
// Only warp-edge lanes (0, 31) fall back to a scalar load.
// GUARD covers the y range (block-uniform, so shuffles stay convergent).
template <bool GUARD>
__device__ __forceinline__ Row load_row(const float* __restrict__ img,
                                        int y, int x, int lane) {
    bool yv = true;
    if (GUARD) yv = (y >= 0) & (y < H);

    float4 c;
    if (GUARD && !yv) {
        c = make_float4(0.f, 0.f, 0.f, 0.f);
    } else {
        c = *reinterpret_cast<const float4*>(img + (size_t)y * W + x);
    }

    Row r;
    r.c = c;
    float up = __shfl_up_sync(0xffffffffu, c.w, 1);
    float dn = __shfl_down_sync(0xffffffffu, c.x, 1);

    if (lane == 0) {
        r.l = (yv && x > 0) ? img[(size_t)y * W + x - 1] : 0.f;
    } else {
        r.l = up;
    }
    if (lane == 31) {
        r.r = (yv && x + 4 < W) ? img[(size_t)y * W + x + 4] : 0.f;
    } else {
        r.r = dn;
    }
    return r;
}

__device__ __forceinline__ float4 hconv(const Row& row, float wl, float wc, float wr) {
    float4 o;
    o.x = fmaf(wl, row.l,   fmaf(wc, row.c.x, wr * row.c.y));
    o.y = fmaf(wl, row.c.x, fmaf(wc, row.c.y, wr * row.c.z));
    o.z = fmaf(wl, row.c.y, fmaf(wc, row.c.z, wr * row.c.w));
    o.w = fmaf(wl, row.c.z, fmaf(wc, row.c.w, wr * row.r));
    return o;
}

// GUARD covers the top strip's y0-1 and the bottom strip's y0+ROWS halo row.
template <bool GUARD>
__device__ __forceinline__ void run_strip(const float* __restrict__ img,
                                          float* __restrict__ out,
                                          const float* __restrict__ w,
                                          int y0, int x, int lane) {
    Row ra = load_row<GUARD>(img, y0 - 1, x, lane);
    Row rb = load_row<false>(img, y0,     x, lane);

#pragma unroll
    for (int i = 0; i < ROWS; i++) {
        int y = y0 + i;
        Row rc = load_row<GUARD>(img, y + 1, x, lane);   // interior: unpredicated

        float4 top = hconv(ra, w[0], w[1], w[2]);
        float4 mid = hconv(rb, w[3], w[4], w[5]);
        float4 bot = hconv(rc, w[6], w[7], w[8]);

        float4 o;
        o.x = top.x + mid.x + bot.x;
        o.y = top.y + mid.y + bot.y;
        o.z = top.z + mid.z + bot.z;
        o.w = top.w + mid.w + bot.w;

        // Plain store (R7 proved __stcs costs ~6us here).
        *reinterpret_cast<float4*>(out + (size_t)y * W + x) = o;

        ra = rb;
        rb = rc;
    }
}

__global__ __launch_bounds__(TPB) void gauss3x3_kernel(
    const float* __restrict__ input,
    const float* __restrict__ weight,
    const float* __restrict__ weight_factor,
    float* __restrict__ output,
    int n_mult)
{
    int z = blockIdx.z;
    int b = z % B;
    int m = z / B;

    // Build the 9-tap kernel (matches reference clamp/round semantics).
    float wf = weight_factor[m];
    wf = clampf(wf, 1.001f, 254.999f);
    wf = clampf(wf, 1.0f, 255.0f);
    float w[9];
#pragma unroll
    for (int k = 0; k < 9; k++) {
        float wc = weight[m * 9 + k];
        wc = clampf(wc, 0.001f, 0.999f);
        wc = clampf(wc, 0.0f, 1.0f);
        float q = rintf(wc * wf);          // RNE, same as jnp.round
        w[k] = fmaxf(q, 0.001f);
    }

    const float* img = input + (size_t)b * H * W;
    float* out = output + ((size_t)m * B + b) * H * W;

    int lane = threadIdx.x & 31;
    int x  = threadIdx.x * 4;
    int y0 = blockIdx.y * ROWS;

    if (blockIdx.y == 0 || blockIdx.y == gridDim.y - 1) {
        run_strip<true>(img, out, w, y0, x, lane);
    } else {
        run_strip<false>(img, out, w, y0, x, lane);
    }
}

extern "C" void kernel_launch(void* const* d_in, const int* in_sizes, int n_in,
                              void* d_out, int out_size) {
    const float* input  = (const float*)d_in[0];
    const float* weight = (const float*)d_in[1];
    const float* wfac   = (const float*)d_in[2];
    float* output       = (float*)d_out;

    int n_mult = in_sizes[1] / 9;   // = 1 for this shape

    dim3 block(TPB, 1, 1);
    dim3 grid(1, H / ROWS, B * n_mult);
    gauss3x3_kernel<<<grid, block>>>(input, weight, wfac, output, n_mult);
}

// round 16
// speedup vs baseline: 1.0790x; 1.0790x over previous
#include <cuda_runtime.h>

// Gaussian_Forward_Model: 3x3 conv, padding=1 (zeros), kernel built from
// weight (clamped) * weight_factor (clamped), rounded (RNE), min-clamped.
// input: [B=64, C=1, H=512, W=512] fp32
// output: [N_MULT, B, 1, H, W] fp32
//
// R10: shared-memory staged tile. Each block loads its 10x512 input tile
// with 10 front-batched coalesced float4 LDGs per thread (MLP ~10), syncs
// once, then computes 8 output rows via register rotation reading rows from
// smem (halo = cheap LDS, not strided global gathers). Plain stores.
// Banned by ledger: __stcs (R7, +6us), shuffle halo (R9, +5us).

#define B 64
#define H 512
#define W 512
#define ROWS 8              // output rows per block-row of threads
#define TILE_ROWS (ROWS + 2)
#define TPB 128             // 128 threads * 4 floats = 512 = W

__device__ __forceinline__ float clampf(float v, float lo, float hi) {
    return fminf(fmaxf(v, lo), hi);
}

struct Row {
    float l;    // x-1
    float4 c;   // x..x+3
    float r;    // x+4
};

__device__ __forceinline__ float4 hconv(const Row& row, float wl, float wc, float wr) {
    float4 o;
    o.x = fmaf(wl, row.l,   fmaf(wc, row.c.x, wr * row.c.y));
    o.y = fmaf(wl, row.c.x, fmaf(wc, row.c.y, wr * row.c.z));
    o.z = fmaf(wl, row.c.y, fmaf(wc, row.c.z, wr * row.c.w));
    o.w = fmaf(wl, row.c.z, fmaf(wc, row.c.w, wr * row.r));
    return o;
}

// Read one tile row into a Row: aligned vector LDS + 2 scalar LDS for halo.
// Only the global image edges (x==0 / x==W-4) need predication.
__device__ __forceinline__ Row row_from_tile(const float* __restrict__ trow, int x) {
    Row r;
    r.c = *reinterpret_cast<const float4*>(trow + x);
    r.l = (x > 0)     ? trow[x - 1] : 0.f;
    r.r = (x + 4 < W) ? trow[x + 4] : 0.f;
    return r;
}

// GUARD: top strip (y0-1 < 0) or bottom strip (y0+ROWS >= H) needs zero rows.
template <bool GUARD>
__device__ __forceinline__ void run_strip(const float* __restrict__ img,
                                          float* __restrict__ out,
                                          const float* __restrict__ w,
                                          float (*tile)[W],
                                          int y0, int x) {
    // Stage the 10-row tile: 10 independent, fully coalesced float4 LDGs.
#pragma unroll
    for (int r = 0; r < TILE_ROWS; r++) {
        int y = y0 - 1 + r;
        float4 v;
        if (GUARD && (y < 0 || y >= H)) {
            v = make_float4(0.f, 0.f, 0.f, 0.f);
        } else {
            v = *reinterpret_cast<const float4*>(img + (size_t)y * W + x);
        }
        *reinterpret_cast<float4*>(&tile[r][x]) = v;
    }
    __syncthreads();

    // Compute with register rotation over smem rows.
    Row ra = row_from_tile(tile[0], x);
    Row rb = row_from_tile(tile[1], x);

#pragma unroll
    for (int i = 0; i < ROWS; i++) {
        Row rc = row_from_tile(tile[i + 2], x);

        float4 top = hconv(ra, w[0], w[1], w[2]);
        float4 mid = hconv(rb, w[3], w[4], w[5]);
        float4 bot = hconv(rc, w[6], w[7], w[8]);

        float4 o;
        o.x = top.x + mid.x + bot.x;
        o.y = top.y + mid.y + bot.y;
        o.z = top.z + mid.z + bot.z;
        o.w = top.w + mid.w + bot.w;

        *reinterpret_cast<float4*>(out + (size_t)(y0 + i) * W + x) = o;

        ra = rb;
        rb = rc;
    }
}

__global__ __launch_bounds__(TPB) void gauss3x3_kernel(
    const float* __restrict__ input,
    const float* __restrict__ weight,
    const float* __restrict__ weight_factor,
    float* __restrict__ output,
    int n_mult)
{
    __shared__ float tile[TILE_ROWS][W];   // 20 KB

    int z = blockIdx.z;
    int b = z % B;
    int m = z / B;

    // Build the 9-tap kernel (matches reference clamp/round semantics).
    float wf = weight_factor[m];
    wf = clampf(wf, 1.001f, 254.999f);
    wf = clampf(wf, 1.0f, 255.0f);
    float w[9];
#pragma unroll
    for (int k = 0; k < 9; k++) {
        float wc = weight[m * 9 + k];
        wc = clampf(wc, 0.001f, 0.999f);
        wc = clampf(wc, 0.0f, 1.0f);
        float q = rintf(wc * wf);          // RNE, same as jnp.round
        w[k] = fmaxf(q, 0.001f);
    }

    const float* img = input + (size_t)b * H * W;
    float* out = output + ((size_t)m * B + b) * H * W;

    int x  = threadIdx.x * 4;
    int y0 = blockIdx.y * ROWS;

    if (blockIdx.y == 0 || blockIdx.y == gridDim.y - 1) {
        run_strip<true>(img, out, w, tile, y0, x);
    } else {
        run_strip<false>(img, out, w, tile, y0, x);
    }
}

extern "C" void kernel_launch(void* const* d_in, const int* in_sizes, int n_in,
                              void* d_out, int out_size) {
    const float* input  = (const float*)d_in[0];
    const float* weight = (const float*)d_in[1];
    const float* wfac   = (const float*)d_in[2];
    float* output       = (float*)d_out;

    int n_mult = in_sizes[1] / 9;   // = 1 for this shape

    dim3 block(TPB, 1, 1);
    dim3 grid(1, H / ROWS, B * n_mult);
    gauss3x3_kernel<<<grid, block>>>(input, weight, wfac, output, n_mult);
}

// round 17
// speedup vs baseline: 1.1915x; 1.1042x over previous
#include <cuda_runtime.h>

// Gaussian_Forward_Model: 3x3 conv, padding=1 (zeros), kernel built from
// weight (clamped) * weight_factor (clamped), rounded (RNE), min-clamped.
// input: [B=64, C=1, H=512, W=512] fp32
// output: [N_MULT, B, 1, H, W] fp32
//
// R11: R8's per-CTA body (scalar halo, plain stores, register rotation)
// with a ONE-WAVE grid. R8 ran 4096 identical CTAs at 16-resident/SM
// (2368 concurrent) = 1.73 waves -> makespan 2*T_strip (13% quantization
// tail). Here: 2368 CTAs exactly (37 chunks/image x 64 images), each chunk
// 13-14 rows (c*512/37 partition). All CTAs resident from t=0; makespan
// drops from 16 row-times to 14.
// Banned by ledger: __stcs (R7), shuffle halo (R9), smem staging (R10),
// ROWS=4 (R5), ROWS=16 (R2).

#define B 64
#define H 512
#define W 512
#define CHUNKS 37           // per image; 37*64 = 2368 = 16 CTAs/SM * 148 SMs
#define TPB 128             // 128 threads * 4 floats = 512 = W

__device__ __forceinline__ float clampf(float v, float lo, float hi) {
    return fminf(fmaxf(v, lo), hi);
}

struct Row {
    float l;    // x-1
    float4 c;   // x..x+3
    float r;    // x+4
};

template <bool GUARD>
__device__ __forceinline__ Row load_row(const float* __restrict__ img, int y, int x) {
    Row row;
    if (GUARD) {
        if (y < 0 || y >= H) {
            row.l = 0.f; row.r = 0.f;
            row.c = make_float4(0.f, 0.f, 0.f, 0.f);
            return row;
        }
    }
    const float* p = img + (size_t)y * W + x;
    row.c = *reinterpret_cast<const float4*>(p);
    row.l = (x > 0)     ? p[-1] : 0.f;
    row.r = (x + 4 < W) ? p[4]  : 0.f;
    return row;
}

__device__ __forceinline__ float4 hconv(const Row& row, float wl, float wc, float wr) {
    float4 o;
    o.x = fmaf(wl, row.l,   fmaf(wc, row.c.x, wr * row.c.y));
    o.y = fmaf(wl, row.c.x, fmaf(wc, row.c.y, wr * row.c.z));
    o.z = fmaf(wl, row.c.y, fmaf(wc, row.c.z, wr * row.c.w));
    o.w = fmaf(wl, row.c.z, fmaf(wc, row.c.w, wr * row.r));
    return o;
}

// GUARD: first chunk (top halo row < 0) or last chunk (bottom halo row == H).
template <bool GUARD>
__device__ __forceinline__ void run_chunk(const float* __restrict__ img,
                                          float* __restrict__ out,
                                          const float* __restrict__ w,
                                          int r0, int r1, int x) {
    Row ra = load_row<GUARD>(img, r0 - 1, x);
    Row rb = load_row<false>(img, r0,     x);

    for (int y = r0; y < r1; y++) {
        Row rc = load_row<GUARD>(img, y + 1, x);   // interior chunks: y+1 < H always

        float4 top = hconv(ra, w[0], w[1], w[2]);
        float4 mid = hconv(rb, w[3], w[4], w[5]);
        float4 bot = hconv(rc, w[6], w[7], w[8]);

        float4 o;
        o.x = top.x + mid.x + bot.x;
        o.y = top.y + mid.y + bot.y;
        o.z = top.z + mid.z + bot.z;
        o.w = top.w + mid.w + bot.w;

        *reinterpret_cast<float4*>(out + (size_t)y * W + x) = o;

        ra = rb;
        rb = rc;
    }
}

__global__ __launch_bounds__(TPB, 16) void gauss3x3_kernel(
    const float* __restrict__ input,
    const float* __restrict__ weight,
    const float* __restrict__ weight_factor,
    float* __restrict__ output,
    int n_mult)
{
    int z = blockIdx.z;
    int b = z % B;
    int m = z / B;

    // Build the 9-tap kernel (matches reference clamp/round semantics).
    float wf = weight_factor[m];
    wf = clampf(wf, 1.001f, 254.999f);
    wf = clampf(wf, 1.0f, 255.0f);
    float w[9];
#pragma unroll
    for (int k = 0; k < 9; k++) {
        float wc = weight[m * 9 + k];
        wc = clampf(wc, 0.001f, 0.999f);
        wc = clampf(wc, 0.0f, 1.0f);
        float q = rintf(wc * wf);          // RNE, same as jnp.round
        w[k] = fmaxf(q, 0.001f);
    }

    const float* img = input + (size_t)b * H * W;
    float* out = output + ((size_t)m * B + b) * H * W;

    int x = threadIdx.x * 4;

    // Balanced partition of H rows into CHUNKS chunks (sizes 13 or 14).
    int c  = blockIdx.y;
    int r0 = (c * H) / CHUNKS;
    int r1 = ((c + 1) * H) / CHUNKS;

    if (c == 0 || c == CHUNKS - 1) {
        run_chunk<true>(img, out, w, r0, r1, x);
    } else {
        run_chunk<false>(img, out, w, r0, r1, x);
    }
}

extern "C" void kernel_launch(void* const* d_in, const int* in_sizes, int n_in,
                              void* d_out, int out_size) {
    const float* input  = (const float*)d_in[0];
    const float* weight = (const float*)d_in[1];
    const float* wfac   = (const float*)d_in[2];
    float* output       = (float*)d_out;

    int n_mult = in_sizes[1] / 9;   // = 1 for this shape

    dim3 block(TPB, 1, 1);
    dim3 grid(1, CHUNKS, B * n_mult);
    gauss3x3_kernel<<<grid, block>>>(input, weight, wfac, output, n_mult);
}